// round 2
// baseline (speedup 1.0000x reference)
#include <cuda_runtime.h>
#include <cstdint>

// ---------------------------------------------------------------------------
// Problem constants (fixed shapes per reference)
//   x0: (2,256,200,304)  x1: (2,256,100,152)  x2: (2,256,50,76)  x3: (2,256,25,38)
//   boxes: (2,512,4)  -> R = 1024 rois
//   out: 4 levels x (1024, 256, 7, 7) f32, concatenated
// ---------------------------------------------------------------------------
#define NLVL 4
#define CCH  256
#define ROUT 7
#define BINS 49
#define RTOT 1024
#define OUT_LVL_STRIDE 12845056   // 1024*256*49
#define ROI_STRIDE     12544      // 256*49

// NHWC scratch: total floats = 2*256*(60800+15200+3800+950) = 41,344,000 (~165 MB)
__device__ float g_nhwc[41344000];

// level geometry
__constant__ int   c_H[NLVL]   = {200, 100, 50, 25};
__constant__ int   c_W[NLVL]   = {304, 152, 76, 38};
__constant__ float c_S[NLVL]   = {0.25f, 0.125f, 0.0625f, 0.03125f};
__constant__ long  c_OFF[NLVL] = {0L, 31129600L, 38912000L, 40857600L};

// ---------------------------------------------------------------------------
// NCHW -> NHWC transpose (32x32 tile in shared)
// grid: ( ceil(W/32), H, B*8 ),  block: (32,8)
// ---------------------------------------------------------------------------
__global__ void transpose_nhwc_kernel(const float* __restrict__ src,
                                      long dst_off, int H, int W)
{
    __shared__ float tile[32][33];
    float* dst = g_nhwc + dst_off;

    const int wt = blockIdx.x * 32;
    const int h  = blockIdx.y;
    const int b  = blockIdx.z >> 3;
    const int c0 = (blockIdx.z & 7) * 32;
    const int tx = threadIdx.x, ty = threadIdx.y;

    const float* s = src + ((size_t)(b * CCH + c0) * H + h) * W;
#pragma unroll
    for (int j = 0; j < 4; j++) {
        int c = ty + j * 8;
        int w = wt + tx;
        tile[c][tx] = (w < W) ? s[(size_t)c * H * W + w] : 0.0f;
    }
    __syncthreads();

    float* d = dst + ((size_t)(b * H + h) * W) * CCH;
#pragma unroll
    for (int j = 0; j < 4; j++) {
        int w = wt + ty + j * 8;
        if (w < W) d[(size_t)w * CCH + (c0 + tx)] = tile[tx][ty + j * 8];
    }
}

// ---------------------------------------------------------------------------
// Main RoI Align kernel.
// grid: 4096 blocks = level*1024 + roi ; block: 256 threads (8 warps)
// Per block:
//   1) 14 threads build separable tap tables (7 y-sets x 4 taps, 7 x-sets x 4 taps)
//   2) warps compute bins; each lane covers 4 channels via float4 (128 ch/half)
//   3) results staged in shared [bin][c], flushed with coalesced STG in (c,bin) order
// ---------------------------------------------------------------------------
__global__ __launch_bounds__(256) void roi_align_kernel(const float* __restrict__ boxes,
                                                        float* __restrict__ out)
{
    __shared__ float s_buf[BINS * 132];      // pad 128 -> 132 (float4-aligned rows)
    __shared__ int   s_yoff[ROUT][4];
    __shared__ float s_yw[ROUT][4];
    __shared__ int   s_xoff[ROUT][4];
    __shared__ float s_xw[ROUT][4];

    const int blk = blockIdx.x;
    const int lvl = blk >> 10;
    const int roi = blk & 1023;
    const int tid = threadIdx.x;

    const int   H = c_H[lvl];
    const int   W = c_W[lvl];
    const float S = c_S[lvl];

    // ---- tap tables: threads 0..6 do y (ph), threads 32..38 do x (pw) ----
    if (tid < ROUT || (tid >= 32 && tid < 32 + ROUT)) {
        const bool isY = (tid < ROUT);
        const int  p   = isY ? tid : (tid - 32);
        const float b1 = boxes[roi * 4 + (isY ? 1 : 0)] * S;   // y1 or x1
        const float b2 = boxes[roi * 4 + (isY ? 3 : 2)] * S;   // y2 or x2
        const float len  = fmaxf(b2 - b1, 1.0f);
        const int   D    = isY ? H : W;
        const float Df   = (float)D;
        const float step = len * (1.0f / (float)ROUT);
        const int   estr = isY ? (W * CCH) : CCH;
#pragma unroll
        for (int s = 0; s < 2; s++) {
            float g   = ((float)(p * 2 + s) + 0.5f) * 0.5f;
            float pos = b1 + step * g;
            bool  v   = (pos >= -1.0f) && (pos <= Df);
            float pc  = fminf(fmaxf(pos, 0.0f), Df - 1.0f);
            int   i0  = (int)floorf(pc);
            int   i1  = min(i0 + 1, D - 1);
            float l   = pc - (float)i0;
            float h   = 1.0f - l;
            float vw  = v ? 0.5f : 0.0f;   // 0.5*0.5 gives the /4 sr^2 mean
            if (isY) {
                s_yoff[p][2 * s]     = i0 * estr;  s_yw[p][2 * s]     = h * vw;
                s_yoff[p][2 * s + 1] = i1 * estr;  s_yw[p][2 * s + 1] = l * vw;
            } else {
                s_xoff[p][2 * s]     = i0 * estr;  s_xw[p][2 * s]     = h * vw;
                s_xoff[p][2 * s + 1] = i1 * estr;  s_xw[p][2 * s + 1] = l * vw;
            }
        }
    }
    __syncthreads();

    const int b = roi >> 9;  // batch
    const float* fbase = g_nhwc + c_OFF[lvl] + (size_t)b * H * W * CCH;
    float* outR = out + (size_t)lvl * OUT_LVL_STRIDE + (size_t)roi * ROI_STRIDE;

    const int warp = tid >> 5;
    const int lane = tid & 31;

#pragma unroll
    for (int half = 0; half < 2; half++) {
        const int cbase = half * 128 + lane * 4;
        for (int bin = warp; bin < BINS; bin += 8) {
            const int ph = bin / 7;
            const int pw = bin - ph * 7;
            float4 acc = make_float4(0.f, 0.f, 0.f, 0.f);
#pragma unroll
            for (int i = 0; i < 4; i++) {
                const float wy = s_yw[ph][i];
                const float* rowp = fbase + s_yoff[ph][i] + cbase;
#pragma unroll
                for (int j = 0; j < 4; j++) {
                    const float w = wy * s_xw[pw][j];
                    const float4 v = *(const float4*)(rowp + s_xoff[pw][j]);
                    acc.x += w * v.x;
                    acc.y += w * v.y;
                    acc.z += w * v.z;
                    acc.w += w * v.w;
                }
            }
            *(float4*)&s_buf[bin * 132 + lane * 4] = acc;
        }
        __syncthreads();
        // flush: out element index within this half = c*49 + bin (coalesced)
        for (int e = tid; e < 128 * BINS; e += 256) {
            int c   = e / 49;
            int bin = e - c * 49;
            outR[half * (128 * BINS) + e] = s_buf[bin * 132 + c];
        }
        __syncthreads();
    }
}

// ---------------------------------------------------------------------------
extern "C" void kernel_launch(void* const* d_in, const int* in_sizes, int n_in,
                              void* d_out, int out_size)
{
    const float* xs[NLVL] = {
        (const float*)d_in[0], (const float*)d_in[1],
        (const float*)d_in[2], (const float*)d_in[3]
    };
    const float* boxes = (const float*)d_in[4];
    float* out = (float*)d_out;

    const int  Hs[NLVL]  = {200, 100, 50, 25};
    const int  Ws[NLVL]  = {304, 152, 76, 38};
    const long off[NLVL] = {0L, 31129600L, 38912000L, 40857600L};

    for (int l = 0; l < NLVL; l++) {
        dim3 grid((Ws[l] + 31) / 32, Hs[l], 2 * 8);
        transpose_nhwc_kernel<<<grid, dim3(32, 8)>>>(xs[l], off[l], Hs[l], Ws[l]);
    }
    roi_align_kernel<<<NLVL * RTOT, 256>>>(boxes, out);
}

// round 3
// speedup vs baseline: 1.3006x; 1.3006x over previous
#include <cuda_runtime.h>
#include <cuda_fp16.h>
#include <cstdint>

// ---------------------------------------------------------------------------
// Shapes: x0 (2,256,200,304) x1 (2,256,100,152) x2 (2,256,50,76) x3 (2,256,25,38)
// boxes (2,512,4) -> 1024 rois; out = 4 levels x (1024,256,7,7) f32 concatenated
// ---------------------------------------------------------------------------
#define NLVL 4
#define CCH  256
#define ROUT 7
#define BINS 49
#define RTOT 1024
#define OUT_LVL_STRIDE 12845056   // 1024*256*49
#define ROI_STRIDE     12544      // 256*49
#define SBUF_PITCH     257        // odd word pitch -> conflict-free flush
#define SBUF_BYTES     (BINS * SBUF_PITCH * 4)   // 50372

// fp16 NHWC scratch: 2*256*(60800+15200+3800+950) = 41,344,000 halves (~83 MB)
__device__ __half g_nhwc[41344000];

__constant__ int   c_H[NLVL]     = {200, 100, 50, 25};
__constant__ int   c_W[NLVL]     = {304, 152, 76, 38};
__constant__ float c_S[NLVL]     = {0.25f, 0.125f, 0.0625f, 0.03125f};
__constant__ int   c_OFF[NLVL]   = {0, 31129600, 38912000, 40857600};
__constant__ int   c_NWT[NLVL]   = {10, 5, 3, 2};
__constant__ int   c_START[NLVL] = {0, 16000, 20000, 21200};  // nwt*H*8 cumulative

// ---------------------------------------------------------------------------
// Fused NCHW(f32) -> NHWC(f16) transpose, all 4 levels in one launch.
// Flat grid of 21600 blocks, block (32,8).
// Per block: 32 w-columns x 64 channels of one (b,h) row.
// ---------------------------------------------------------------------------
__global__ __launch_bounds__(256) void transpose_half_kernel(
    const float* __restrict__ x0, const float* __restrict__ x1,
    const float* __restrict__ x2, const float* __restrict__ x3)
{
    __shared__ float tile[64][33];

    const int bid = blockIdx.x;
    int lvl;
    if      (bid >= c_START[3]) lvl = 3;
    else if (bid >= c_START[2]) lvl = 2;
    else if (bid >= c_START[1]) lvl = 1;
    else                        lvl = 0;

    const int H = c_H[lvl], W = c_W[lvl], nwt = c_NWT[lvl];
    const int r    = bid - c_START[lvl];
    const int z    = r / (nwt * H);
    const int rem  = r - z * (nwt * H);
    const int h    = rem / nwt;
    const int wt   = (rem - h * nwt) * 32;
    const int b    = z >> 2;
    const int c0   = (z & 3) * 64;

    const float* src = (lvl == 0) ? x0 : (lvl == 1) ? x1 : (lvl == 2) ? x2 : x3;
    const int tx = threadIdx.x, ty = threadIdx.y;

    // read: coalesced along w; store stride-1 rows -> conflict-free
    {
        const int w = wt + tx;
        const float* s = src + ((size_t)(b * CCH + c0) * H + h) * W;
#pragma unroll
        for (int j = 0; j < 8; j++) {
            int c = ty + j * 8;
            tile[c][tx] = (w < W) ? s[(size_t)c * H * W + w] : 0.0f;
        }
    }
    __syncthreads();

    // write: warp covers 32 consecutive halves of the NHWC row (64B/inst);
    // smem reads stride-33 down a column -> conflict-free
    __half* dst = g_nhwc + c_OFF[lvl] + ((size_t)(b * H + h) * W) * CCH;
#pragma unroll
    for (int jj = 0; jj < 4; jj++) {
        int wl = ty + jj * 8;
        int w  = wt + wl;
        if (w < W) {
#pragma unroll
            for (int cc = 0; cc < 2; cc++) {
                int cl = cc * 32 + tx;
                dst[(size_t)w * CCH + c0 + cl] = __float2half(tile[cl][wl]);
            }
        }
    }
}

// ---------------------------------------------------------------------------
// RoI Align main kernel. grid 4096 = lvl*1024+roi ; 256 threads (8 warps).
// One warp computes a full bin (all 256 channels: lane -> 8 ch via LDG.128).
// Staged in dynamic smem (fp32, pitch 257, (k*32+lane) interleave), flushed
// fully coalesced in (c,bin) order.
// ---------------------------------------------------------------------------
extern __shared__ float s_buf[];

__global__ __launch_bounds__(256) void roi_align_kernel(const float* __restrict__ boxes,
                                                        float* __restrict__ out)
{
    __shared__ int   s_yoff[ROUT][4];
    __shared__ float s_yw[ROUT][4];
    __shared__ int   s_xoff[ROUT][4];
    __shared__ float s_xw[ROUT][4];

    const int blk = blockIdx.x;
    const int lvl = blk >> 10;
    const int roi = blk & 1023;
    const int tid = threadIdx.x;

    const int   H = c_H[lvl];
    const int   W = c_W[lvl];
    const float S = c_S[lvl];

    // tap tables: threads 0..6 -> y, 32..38 -> x
    if (tid < ROUT || (tid >= 32 && tid < 32 + ROUT)) {
        const bool isY = (tid < ROUT);
        const int  p   = isY ? tid : (tid - 32);
        const float b1 = boxes[roi * 4 + (isY ? 1 : 0)] * S;
        const float b2 = boxes[roi * 4 + (isY ? 3 : 2)] * S;
        const float len  = fmaxf(b2 - b1, 1.0f);
        const int   D    = isY ? H : W;
        const float Df   = (float)D;
        const float step = len * (1.0f / (float)ROUT);
        const int   estr = isY ? (W * CCH) : CCH;   // half-element strides
#pragma unroll
        for (int s = 0; s < 2; s++) {
            float g   = ((float)(p * 2 + s) + 0.5f) * 0.5f;
            float pos = b1 + step * g;
            bool  v   = (pos >= -1.0f) && (pos <= Df);
            float pc  = fminf(fmaxf(pos, 0.0f), Df - 1.0f);
            int   i0  = (int)floorf(pc);
            int   i1  = min(i0 + 1, D - 1);
            float l   = pc - (float)i0;
            float hgt = 1.0f - l;
            float vw  = v ? 0.5f : 0.0f;   // 0.5*0.5 realizes the sr^2 mean
            if (isY) {
                s_yoff[p][2 * s]     = i0 * estr;  s_yw[p][2 * s]     = hgt * vw;
                s_yoff[p][2 * s + 1] = i1 * estr;  s_yw[p][2 * s + 1] = l * vw;
            } else {
                s_xoff[p][2 * s]     = i0 * estr;  s_xw[p][2 * s]     = hgt * vw;
                s_xoff[p][2 * s + 1] = i1 * estr;  s_xw[p][2 * s + 1] = l * vw;
            }
        }
    }
    __syncthreads();

    const int b = roi >> 9;
    const __half* fbase = g_nhwc + c_OFF[lvl] + (size_t)b * H * W * CCH;
    float* outR = out + (size_t)lvl * OUT_LVL_STRIDE + (size_t)roi * ROI_STRIDE;

    const int warp = tid >> 5;
    const int lane = tid & 31;
    const int cbase = lane * 8;     // 8 channels per lane (16B)

    for (int bin = warp; bin < BINS; bin += 8) {
        const int ph = bin / 7;
        const int pw = bin - ph * 7;
        float2 a0 = {0.f, 0.f}, a1 = {0.f, 0.f}, a2 = {0.f, 0.f}, a3 = {0.f, 0.f};
#pragma unroll
        for (int i = 0; i < 4; i++) {
            const float wy = s_yw[ph][i];
            const __half* rp = fbase + s_yoff[ph][i] + cbase;
#pragma unroll
            for (int j = 0; j < 4; j++) {
                const float w = wy * s_xw[pw][j];
                const uint4 v = *(const uint4*)(rp + s_xoff[pw][j]);
                const __half2* hp = (const __half2*)&v;
                float2 f;
                f = __half22float2(hp[0]); a0.x = fmaf(w, f.x, a0.x); a0.y = fmaf(w, f.y, a0.y);
                f = __half22float2(hp[1]); a1.x = fmaf(w, f.x, a1.x); a1.y = fmaf(w, f.y, a1.y);
                f = __half22float2(hp[2]); a2.x = fmaf(w, f.x, a2.x); a2.y = fmaf(w, f.y, a2.y);
                f = __half22float2(hp[3]); a3.x = fmaf(w, f.x, a3.x); a3.y = fmaf(w, f.y, a3.y);
            }
        }
        // interleaved store: word p = k*32+lane holds channel lane*8+k
        float vals[8] = {a0.x, a0.y, a1.x, a1.y, a2.x, a2.y, a3.x, a3.y};
        const int rb = bin * SBUF_PITCH;
#pragma unroll
        for (int k = 0; k < 8; k++)
            s_buf[rb + k * 32 + lane] = vals[k];
    }
    __syncthreads();

    // flush: out element e = c*49 + bin, fully coalesced; smem stride 257 -> no conflicts
    int e = tid;
    int c = tid / BINS;
    int bin = tid - c * BINS;
#pragma unroll 7
    for (int it = 0; it < BINS; it++) {
        outR[e] = s_buf[bin * SBUF_PITCH + ((c & 7) << 5) + (c >> 3)];
        e += 256;
        bin += 11; c += 5;                 // 256 = 5*49 + 11
        if (bin >= BINS) { bin -= BINS; c += 1; }
    }
}

// ---------------------------------------------------------------------------
extern "C" void kernel_launch(void* const* d_in, const int* in_sizes, int n_in,
                              void* d_out, int out_size)
{
    const float* x0 = (const float*)d_in[0];
    const float* x1 = (const float*)d_in[1];
    const float* x2 = (const float*)d_in[2];
    const float* x3 = (const float*)d_in[3];
    const float* boxes = (const float*)d_in[4];
    float* out = (float*)d_out;

    cudaFuncSetAttribute(roi_align_kernel,
                         cudaFuncAttributeMaxDynamicSharedMemorySize, SBUF_BYTES);

    transpose_half_kernel<<<21600, dim3(32, 8)>>>(x0, x1, x2, x3);
    roi_align_kernel<<<NLVL * RTOT, 256, SBUF_BYTES>>>(boxes, out);
}

// round 6
// speedup vs baseline: 1.5110x; 1.1618x over previous
#include <cuda_runtime.h>
#include <cuda_fp16.h>
#include <cstdint>

// ---------------------------------------------------------------------------
// Shapes: x0 (2,256,200,304) x1 (2,256,100,152) x2 (2,256,50,76) x3 (2,256,25,38)
// boxes (2,512,4) -> 1024 rois; out = 4 levels x (1024,256,7,7) f32 concatenated
// ---------------------------------------------------------------------------
#define NLVL 4
#define CCH  256
#define ROUT 7
#define BINS 49
#define RTOT 1024
#define OUT_LVL_STRIDE 12845056   // 1024*256*49
#define ROI_STRIDE     12544      // 256*49
#define SBUF_PITCH     257        // odd word pitch -> conflict-free flush
#define SBUF_BYTES     (BINS * SBUF_PITCH * 4)   // 50372

// fp16 NHWC scratch: 2*256*(60800+15200+3800+950) = 41,344,000 halves (~83 MB)
__device__ __half g_nhwc[41344000];

__constant__ int   c_H[NLVL]     = {200, 100, 50, 25};
__constant__ int   c_W[NLVL]     = {304, 152, 76, 38};
__constant__ float c_S[NLVL]     = {0.25f, 0.125f, 0.0625f, 0.03125f};
__constant__ int   c_OFF[NLVL]   = {0, 31129600, 38912000, 40857600};
__constant__ int   c_NWT[NLVL]   = {10, 5, 3, 2};
__constant__ int   c_START[NLVL] = {0, 16000, 20000, 21200};

// ---------------------------------------------------------------------------
// Fused NCHW(f32) -> NHWC(f16) transpose, all 4 levels, one launch.
// Block (32,8) covers 32 w x 64 channels of one (b,h) row.
// Phase 1 converts to __half2 (channel pairs) in smem; phase 2 does full
// 128B stores (lane writes one half2). Both phases bank-conflict-free.
// ---------------------------------------------------------------------------
__global__ __launch_bounds__(256) void transpose_half_kernel(
    const float* __restrict__ x0, const float* __restrict__ x1,
    const float* __restrict__ x2, const float* __restrict__ x3)
{
    __shared__ __half2 tile[32][33];     // [c2][w]

    const int bid = blockIdx.x;
    int lvl;
    if      (bid >= c_START[3]) lvl = 3;
    else if (bid >= c_START[2]) lvl = 2;
    else if (bid >= c_START[1]) lvl = 1;
    else                        lvl = 0;

    const int H = c_H[lvl], W = c_W[lvl], nwt = c_NWT[lvl];
    const int r   = bid - c_START[lvl];
    const int z   = r / (nwt * H);
    const int rem = r - z * (nwt * H);
    const int h   = rem / nwt;
    const int wt  = (rem - h * nwt) * 32;
    const int b   = z >> 2;
    const int c0  = (z & 3) * 64;

    const float* src = (lvl == 0) ? x0 : (lvl == 1) ? x1 : (lvl == 2) ? x2 : x3;
    const int tx = threadIdx.x, ty = threadIdx.y;

    const int w = wt + tx;
    if (w < W) {
        const float* s = src + ((size_t)(b * CCH + c0) * H + h) * W + w;
        const size_t plane = (size_t)H * W;
#pragma unroll
        for (int j = 0; j < 4; j++) {
            int c2 = ty + j * 8;
            float lo = s[(size_t)(2 * c2) * plane];
            float hi = s[(size_t)(2 * c2 + 1) * plane];
            tile[c2][tx] = __floats2half2_rn(lo, hi);
        }
    }
    __syncthreads();

    __half2* dst = (__half2*)(g_nhwc + c_OFF[lvl]) +
                   ((size_t)(b * H + h) * W) * (CCH / 2) + (c0 >> 1);
#pragma unroll
    for (int jj = 0; jj < 4; jj++) {
        int wl = ty + jj * 8;
        int ww = wt + wl;
        if (ww < W) dst[(size_t)ww * (CCH / 2) + tx] = tile[tx][wl];
    }
}

// ---------------------------------------------------------------------------
// RoI Align main kernel. grid 4096 = lvl*1024+roi ; 256 threads (8 warps).
// One warp per bin (256 ch: lane -> 8 ch via one LDG.128 per tap).
// x-taps accumulated in fp16 (HFMA2), y-combine in packed f32x2 (FFMA2).
// ---------------------------------------------------------------------------
extern __shared__ float s_buf[];

typedef unsigned long long u64t;
union F2U { float2 f; u64t u; };

__global__ __launch_bounds__(256) void roi_align_kernel(const float* __restrict__ boxes,
                                                        float* __restrict__ out)
{
    __shared__ int     s_yoff[ROUT][4];
    __shared__ u64t    s_yw2[ROUT][4];     // packed (wy,wy) f32x2
    __shared__ int     s_xoff[ROUT][4];
    __shared__ __half2 s_xwh[ROUT][4];     // (wx,wx) half2

    const int blk = blockIdx.x;
    const int lvl = blk >> 10;
    const int roi = blk & 1023;
    const int tid = threadIdx.x;

    const int   H = c_H[lvl];
    const int   W = c_W[lvl];
    const float S = c_S[lvl];

    // tap tables: threads 0..6 -> y, 32..38 -> x
    if (tid < ROUT || (tid >= 32 && tid < 32 + ROUT)) {
        const bool isY = (tid < ROUT);
        const int  p   = isY ? tid : (tid - 32);
        const float b1 = boxes[roi * 4 + (isY ? 1 : 0)] * S;
        const float b2 = boxes[roi * 4 + (isY ? 3 : 2)] * S;
        const float len  = fmaxf(b2 - b1, 1.0f);
        const int   D    = isY ? H : W;
        const float Df   = (float)D;
        const float step = len * (1.0f / (float)ROUT);
        const int   estr = isY ? (W * CCH) : CCH;   // strides in halves
#pragma unroll
        for (int s = 0; s < 2; s++) {
            float g   = ((float)(p * 2 + s) + 0.5f) * 0.5f;
            float pos = b1 + step * g;
            bool  v   = (pos >= -1.0f) && (pos <= Df);
            float pc  = fminf(fmaxf(pos, 0.0f), Df - 1.0f);
            int   i0  = (int)floorf(pc);
            int   i1  = min(i0 + 1, D - 1);
            float l   = pc - (float)i0;
            float hgt = 1.0f - l;
            float vw  = v ? 0.5f : 0.0f;   // 0.5*0.5 realizes the sr^2 mean
            if (isY) {
                unsigned u0 = __float_as_uint(hgt * vw);
                unsigned u1 = __float_as_uint(l * vw);
                s_yoff[p][2 * s]     = i0 * estr;
                s_yoff[p][2 * s + 1] = i1 * estr;
                s_yw2[p][2 * s]      = ((u64t)u0 << 32) | u0;
                s_yw2[p][2 * s + 1]  = ((u64t)u1 << 32) | u1;
            } else {
                s_xoff[p][2 * s]     = i0 * estr;
                s_xoff[p][2 * s + 1] = i1 * estr;
                s_xwh[p][2 * s]      = __float2half2_rn(hgt * vw);
                s_xwh[p][2 * s + 1]  = __float2half2_rn(l * vw);
            }
        }
    }
    __syncthreads();

    const int b = roi >> 9;
    const __half* fbase = g_nhwc + c_OFF[lvl] + (size_t)b * H * W * CCH;
    float* outR = out + (size_t)lvl * OUT_LVL_STRIDE + (size_t)roi * ROI_STRIDE;

    const int warp = tid >> 5;
    const int lane = tid & 31;
    const int cbase = lane * 8;     // 8 channels per lane

    for (int bin = warp; bin < BINS; bin += 8) {
        const int ph = bin / 7;
        const int pw = bin - ph * 7;

        u64t acc0 = 0, acc1 = 0, acc2 = 0, acc3 = 0;
#pragma unroll
        for (int i = 0; i < 4; i++) {
            const __half* rp = fbase + s_yoff[ph][i] + cbase;
            __half2 r0 = __float2half2_rn(0.f), r1 = r0, r2 = r0, r3 = r0;
#pragma unroll
            for (int j = 0; j < 4; j++) {
                const __half2 w2 = s_xwh[pw][j];
                const uint4 v = *(const uint4*)(rp + s_xoff[pw][j]);
                const __half2* hp = (const __half2*)&v;
                r0 = __hfma2(w2, hp[0], r0);
                r1 = __hfma2(w2, hp[1], r1);
                r2 = __hfma2(w2, hp[2], r2);
                r3 = __hfma2(w2, hp[3], r3);
            }
            const u64t wy2 = s_yw2[ph][i];
            F2U f0, f1, f2, f3;
            f0.f = __half22float2(r0);
            f1.f = __half22float2(r1);
            f2.f = __half22float2(r2);
            f3.f = __half22float2(r3);
            asm("fma.rn.f32x2 %0, %1, %2, %0;" : "+l"(acc0) : "l"(f0.u), "l"(wy2));
            asm("fma.rn.f32x2 %0, %1, %2, %0;" : "+l"(acc1) : "l"(f1.u), "l"(wy2));
            asm("fma.rn.f32x2 %0, %1, %2, %0;" : "+l"(acc2) : "l"(f2.u), "l"(wy2));
            asm("fma.rn.f32x2 %0, %1, %2, %0;" : "+l"(acc3) : "l"(f3.u), "l"(wy2));
        }

        // interleaved store: word k*32+lane holds channel cbase+k
        F2U o0, o1, o2, o3;
        o0.u = acc0; o1.u = acc1; o2.u = acc2; o3.u = acc3;
        float vals[8] = {o0.f.x, o0.f.y, o1.f.x, o1.f.y,
                         o2.f.x, o2.f.y, o3.f.x, o3.f.y};
        const int rb = bin * SBUF_PITCH;
#pragma unroll
        for (int k = 0; k < 8; k++)
            s_buf[rb + k * 32 + lane] = vals[k];
    }
    __syncthreads();

    // flush: out element e = c*49 + bin, fully coalesced; pitch 257 -> no conflicts
    int e = tid;
    int c = tid / BINS;
    int bin = tid - c * BINS;
#pragma unroll 7
    for (int it = 0; it < BINS; it++) {
        outR[e] = s_buf[bin * SBUF_PITCH + ((c & 7) << 5) + (c >> 3)];
        e += 256;
        bin += 11; c += 5;                 // 256 = 5*49 + 11
        if (bin >= BINS) { bin -= BINS; c += 1; }
    }
}

// ---------------------------------------------------------------------------
extern "C" void kernel_launch(void* const* d_in, const int* in_sizes, int n_in,
                              void* d_out, int out_size)
{
    const float* x0 = (const float*)d_in[0];
    const float* x1 = (const float*)d_in[1];
    const float* x2 = (const float*)d_in[2];
    const float* x3 = (const float*)d_in[3];
    const float* boxes = (const float*)d_in[4];
    float* out = (float*)d_out;

    cudaFuncSetAttribute(roi_align_kernel,
                         cudaFuncAttributeMaxDynamicSharedMemorySize, SBUF_BYTES);

    transpose_half_kernel<<<21600, dim3(32, 8)>>>(x0, x1, x2, x3);
    roi_align_kernel<<<NLVL * RTOT, 256, SBUF_BYTES>>>(boxes, out);
}

// round 7
// speedup vs baseline: 1.6379x; 1.0839x over previous
#include <cuda_runtime.h>
#include <cuda_fp16.h>
#include <cstdint>

// ---------------------------------------------------------------------------
// Shapes: x0 (2,256,200,304) x1 (2,256,100,152) x2 (2,256,50,76) x3 (2,256,25,38)
// boxes (2,512,4) -> 1024 rois; out = 4 levels x (1024,256,7,7) f32 concatenated
// ---------------------------------------------------------------------------
#define NLVL 4
#define CCH  256
#define ROUT 7
#define BINS 49
#define RTOT 1024
#define OUT_LVL_STRIDE 12845056   // 1024*256*49
#define ROI_STRIDE     12544      // 256*49
#define SBUF_PITCH     257        // odd word pitch -> conflict-free flush
#define SBUF_BYTES     (BINS * SBUF_PITCH * 4)   // 50372

// fp16 NHWC scratch: 2*256*(60800+15200+3800+950) = 41,344,000 halves (~83 MB)
__device__ __half g_nhwc[41344000];

__constant__ int   c_H[NLVL]     = {200, 100, 50, 25};
__constant__ int   c_W[NLVL]     = {304, 152, 76, 38};
__constant__ float c_S[NLVL]     = {0.25f, 0.125f, 0.0625f, 0.03125f};
__constant__ int   c_OFF[NLVL]   = {0, 31129600, 38912000, 40857600};
__constant__ int   c_NWT[NLVL]   = {10, 5, 3, 2};
__constant__ int   c_START[NLVL] = {0, 16000, 20000, 21200};

// ---------------------------------------------------------------------------
// Fused NCHW(f32) -> NHWC(f16) transpose, all 4 levels, one launch.
// ---------------------------------------------------------------------------
__global__ __launch_bounds__(256) void transpose_half_kernel(
    const float* __restrict__ x0, const float* __restrict__ x1,
    const float* __restrict__ x2, const float* __restrict__ x3)
{
    __shared__ __half2 tile[32][33];     // [c2][w]

    const int bid = blockIdx.x;
    int lvl;
    if      (bid >= c_START[3]) lvl = 3;
    else if (bid >= c_START[2]) lvl = 2;
    else if (bid >= c_START[1]) lvl = 1;
    else                        lvl = 0;

    const int H = c_H[lvl], W = c_W[lvl], nwt = c_NWT[lvl];
    const int r   = bid - c_START[lvl];
    const int z   = r / (nwt * H);
    const int rem = r - z * (nwt * H);
    const int h   = rem / nwt;
    const int wt  = (rem - h * nwt) * 32;
    const int b   = z >> 2;
    const int c0  = (z & 3) * 64;

    const float* src = (lvl == 0) ? x0 : (lvl == 1) ? x1 : (lvl == 2) ? x2 : x3;
    const int tx = threadIdx.x, ty = threadIdx.y;

    const int w = wt + tx;
    if (w < W) {
        const float* s = src + ((size_t)(b * CCH + c0) * H + h) * W + w;
        const size_t plane = (size_t)H * W;
#pragma unroll
        for (int j = 0; j < 4; j++) {
            int c2 = ty + j * 8;
            float lo = s[(size_t)(2 * c2) * plane];
            float hi = s[(size_t)(2 * c2 + 1) * plane];
            tile[c2][tx] = __floats2half2_rn(lo, hi);
        }
    }
    __syncthreads();

    __half2* dst = (__half2*)(g_nhwc + c_OFF[lvl]) +
                   ((size_t)(b * H + h) * W) * (CCH / 2) + (c0 >> 1);
#pragma unroll
    for (int jj = 0; jj < 4; jj++) {
        int wl = ty + jj * 8;
        int ww = wt + wl;
        if (ww < W) dst[(size_t)ww * (CCH / 2) + tx] = tile[tx][wl];
    }
}

// ---------------------------------------------------------------------------
// RoI Align main kernel. grid 4096 = lvl*1024+roi ; 256 threads (8 warps).
// One warp per bin (256 ch: lane -> 8 ch via one LDG.128 per tap).
// Tap tables MERGE duplicate pixel offsets (weight sum, dup weight -> 0);
// the 4x4 loop skips zero-weight taps with warp-uniform branches, killing
// the redundant LDG traffic at coarse FPN levels.
// x-taps accumulated in fp16 (HFMA2), y-combine in packed f32x2 (FFMA2).
// ---------------------------------------------------------------------------
extern __shared__ float s_buf[];

typedef unsigned long long u64t;
union F2U { float2 f; u64t u; };

__global__ __launch_bounds__(256) void roi_align_kernel(const float* __restrict__ boxes,
                                                        float* __restrict__ out)
{
    __shared__ int      s_yoff[ROUT][4];
    __shared__ u64t     s_yw2[ROUT][4];     // packed (wy,wy) f32x2; 0 => skip row
    __shared__ int      s_xoff[ROUT][4];
    __shared__ unsigned s_xwu[ROUT][4];     // (wx,wx) half2 bits;  0 => skip tap

    const int blk = blockIdx.x;
    const int lvl = blk >> 10;
    const int roi = blk & 1023;
    const int tid = threadIdx.x;

    const int   H = c_H[lvl];
    const int   W = c_W[lvl];
    const float S = c_S[lvl];

    // tap tables: threads 0..6 -> y, 32..38 -> x
    if (tid < ROUT || (tid >= 32 && tid < 32 + ROUT)) {
        const bool isY = (tid < ROUT);
        const int  p   = isY ? tid : (tid - 32);
        const float b1 = boxes[roi * 4 + (isY ? 1 : 0)] * S;
        const float b2 = boxes[roi * 4 + (isY ? 3 : 2)] * S;
        const float len  = fmaxf(b2 - b1, 1.0f);
        const int   D    = isY ? H : W;
        const float Df   = (float)D;
        const float step = len * (1.0f / (float)ROUT);
        const int   estr = isY ? (W * CCH) : CCH;   // strides in halves

        int   off[4];
        float wv[4];
#pragma unroll
        for (int s = 0; s < 2; s++) {
            float g   = ((float)(p * 2 + s) + 0.5f) * 0.5f;
            float pos = b1 + step * g;
            bool  v   = (pos >= -1.0f) && (pos <= Df);
            float pc  = fminf(fmaxf(pos, 0.0f), Df - 1.0f);
            int   i0  = (int)floorf(pc);
            int   i1  = min(i0 + 1, D - 1);
            float l   = pc - (float)i0;
            float hgt = 1.0f - l;
            float vw  = v ? 0.5f : 0.0f;   // 0.5*0.5 realizes the sr^2 mean
            off[2 * s]     = i0 * estr;  wv[2 * s]     = hgt * vw;
            off[2 * s + 1] = i1 * estr;  wv[2 * s + 1] = l * vw;
        }
        // merge duplicate offsets (also covers border-clamped i0==i1)
#pragma unroll
        for (int k = 1; k < 4; k++) {
#pragma unroll
            for (int m = 0; m < k; m++) {
                if (off[k] == off[m] && wv[k] != 0.0f && wv[m] != 0.0f) {
                    wv[m] += wv[k];
                    wv[k] = 0.0f;
                }
            }
        }
        if (isY) {
#pragma unroll
            for (int k = 0; k < 4; k++) {
                s_yoff[p][k] = off[k];
                unsigned u = __float_as_uint(wv[k]);
                s_yw2[p][k] = ((u64t)u << 32) | u;     // 0.0f packs to 0
            }
        } else {
#pragma unroll
            for (int k = 0; k < 4; k++) {
                s_xoff[p][k] = off[k];
                __half2 h2 = __float2half2_rn(wv[k]);
                s_xwu[p][k] = *(unsigned*)&h2;          // 0.0f packs to 0
            }
        }
    }
    __syncthreads();

    const int b = roi >> 9;
    const __half* fbase = g_nhwc + c_OFF[lvl] + (size_t)b * H * W * CCH;
    float* outR = out + (size_t)lvl * OUT_LVL_STRIDE + (size_t)roi * ROI_STRIDE;

    const int warp = tid >> 5;
    const int lane = tid & 31;
    const int cbase = lane * 8;     // 8 channels per lane

    for (int bin = warp; bin < BINS; bin += 8) {
        const int ph = bin / 7;
        const int pw = bin - ph * 7;

        u64t acc0 = 0, acc1 = 0, acc2 = 0, acc3 = 0;
#pragma unroll
        for (int i = 0; i < 4; i++) {
            const u64t wy2 = s_yw2[ph][i];
            if (wy2 == 0) continue;                    // warp-uniform: skip 4 LDGs
            const __half* rp = fbase + s_yoff[ph][i] + cbase;
            __half2 r0 = __float2half2_rn(0.f), r1 = r0, r2 = r0, r3 = r0;
#pragma unroll
            for (int j = 0; j < 4; j++) {
                const unsigned wb = s_xwu[pw][j];
                if (wb == 0) continue;                 // warp-uniform: skip 1 LDG
                const __half2 w2 = *(const __half2*)&wb;
                const uint4 v = *(const uint4*)(rp + s_xoff[pw][j]);
                const __half2* hp = (const __half2*)&v;
                r0 = __hfma2(w2, hp[0], r0);
                r1 = __hfma2(w2, hp[1], r1);
                r2 = __hfma2(w2, hp[2], r2);
                r3 = __hfma2(w2, hp[3], r3);
            }
            F2U f0, f1, f2, f3;
            f0.f = __half22float2(r0);
            f1.f = __half22float2(r1);
            f2.f = __half22float2(r2);
            f3.f = __half22float2(r3);
            asm("fma.rn.f32x2 %0, %1, %2, %0;" : "+l"(acc0) : "l"(f0.u), "l"(wy2));
            asm("fma.rn.f32x2 %0, %1, %2, %0;" : "+l"(acc1) : "l"(f1.u), "l"(wy2));
            asm("fma.rn.f32x2 %0, %1, %2, %0;" : "+l"(acc2) : "l"(f2.u), "l"(wy2));
            asm("fma.rn.f32x2 %0, %1, %2, %0;" : "+l"(acc3) : "l"(f3.u), "l"(wy2));
        }

        // interleaved store: word k*32+lane holds channel cbase+k
        F2U o0, o1, o2, o3;
        o0.u = acc0; o1.u = acc1; o2.u = acc2; o3.u = acc3;
        float vals[8] = {o0.f.x, o0.f.y, o1.f.x, o1.f.y,
                         o2.f.x, o2.f.y, o3.f.x, o3.f.y};
        const int rb = bin * SBUF_PITCH;
#pragma unroll
        for (int k = 0; k < 8; k++)
            s_buf[rb + k * 32 + lane] = vals[k];
    }
    __syncthreads();

    // flush: out element e = c*49 + bin, fully coalesced; pitch 257 -> no conflicts
    int e = tid;
    int c = tid / BINS;
    int bin = tid - c * BINS;
#pragma unroll 7
    for (int it = 0; it < BINS; it++) {
        outR[e] = s_buf[bin * SBUF_PITCH + ((c & 7) << 5) + (c >> 3)];
        e += 256;
        bin += 11; c += 5;                 // 256 = 5*49 + 11
        if (bin >= BINS) { bin -= BINS; c += 1; }
    }
}

// ---------------------------------------------------------------------------
extern "C" void kernel_launch(void* const* d_in, const int* in_sizes, int n_in,
                              void* d_out, int out_size)
{
    const float* x0 = (const float*)d_in[0];
    const float* x1 = (const float*)d_in[1];
    const float* x2 = (const float*)d_in[2];
    const float* x3 = (const float*)d_in[3];
    const float* boxes = (const float*)d_in[4];
    float* out = (float*)d_out;

    cudaFuncSetAttribute(roi_align_kernel,
                         cudaFuncAttributeMaxDynamicSharedMemorySize, SBUF_BYTES);

    transpose_half_kernel<<<21600, dim3(32, 8)>>>(x0, x1, x2, x3);
    roi_align_kernel<<<NLVL * RTOT, 256, SBUF_BYTES>>>(boxes, out);
}

// round 8
// speedup vs baseline: 1.7307x; 1.0567x over previous
#include <cuda_runtime.h>
#include <cuda_fp16.h>
#include <cstdint>

// ---------------------------------------------------------------------------
// Shapes: x0 (2,256,200,304) x1 (2,256,100,152) x2 (2,256,50,76) x3 (2,256,25,38)
// boxes (2,512,4) -> 1024 rois; out = 4 levels x (1024,256,7,7) f32 concatenated
// ---------------------------------------------------------------------------
#define NLVL 4
#define CCH  256
#define ROUT 7
#define BINS 49
#define RTOT 1024
#define OUT_LVL_STRIDE 12845056   // 1024*256*49
#define ROI_STRIDE     12544      // 256*49
#define SBUF_PITCHW    129        // words per bin row (128 data + 1 pad; 129%32==1)
#define SBUF_BYTES     (BINS * SBUF_PITCHW * 4)   // 25284 B

// fp16 NHWC scratch: 2*256*(60800+15200+3800+950) = 41,344,000 halves (~83 MB)
__device__ __half g_nhwc[41344000];

__constant__ int   c_H[NLVL]     = {200, 100, 50, 25};
__constant__ int   c_W[NLVL]     = {304, 152, 76, 38};
__constant__ float c_S[NLVL]     = {0.25f, 0.125f, 0.0625f, 0.03125f};
__constant__ int   c_OFF[NLVL]   = {0, 31129600, 38912000, 40857600};
__constant__ int   c_NWT[NLVL]   = {10, 5, 3, 2};
__constant__ int   c_START[NLVL] = {0, 16000, 20000, 21200};

// ---------------------------------------------------------------------------
// Fused NCHW(f32) -> NHWC(f16) transpose, all 4 levels, one launch.
// ---------------------------------------------------------------------------
__global__ __launch_bounds__(256) void transpose_half_kernel(
    const float* __restrict__ x0, const float* __restrict__ x1,
    const float* __restrict__ x2, const float* __restrict__ x3)
{
    __shared__ __half2 tile[32][33];     // [c2][w]

    const int bid = blockIdx.x;
    int lvl;
    if      (bid >= c_START[3]) lvl = 3;
    else if (bid >= c_START[2]) lvl = 2;
    else if (bid >= c_START[1]) lvl = 1;
    else                        lvl = 0;

    const int H = c_H[lvl], W = c_W[lvl], nwt = c_NWT[lvl];
    const int r   = bid - c_START[lvl];
    const int z   = r / (nwt * H);
    const int rem = r - z * (nwt * H);
    const int h   = rem / nwt;
    const int wt  = (rem - h * nwt) * 32;
    const int b   = z >> 2;
    const int c0  = (z & 3) * 64;

    const float* src = (lvl == 0) ? x0 : (lvl == 1) ? x1 : (lvl == 2) ? x2 : x3;
    const int tx = threadIdx.x, ty = threadIdx.y;

    const int w = wt + tx;
    if (w < W) {
        const float* s = src + ((size_t)(b * CCH + c0) * H + h) * W + w;
        const size_t plane = (size_t)H * W;
#pragma unroll
        for (int j = 0; j < 4; j++) {
            int c2 = ty + j * 8;
            float lo = s[(size_t)(2 * c2) * plane];
            float hi = s[(size_t)(2 * c2 + 1) * plane];
            tile[c2][tx] = __floats2half2_rn(lo, hi);
        }
    }
    __syncthreads();

    __half2* dst = (__half2*)(g_nhwc + c_OFF[lvl]) +
                   ((size_t)(b * H + h) * W) * (CCH / 2) + (c0 >> 1);
#pragma unroll
    for (int jj = 0; jj < 4; jj++) {
        int wl = ty + jj * 8;
        int ww = wt + wl;
        if (ww < W) dst[(size_t)ww * (CCH / 2) + tx] = tile[tx][wl];
    }
}

// ---------------------------------------------------------------------------
// RoI Align main kernel. grid 4096 = lvl*1024+roi ; 256 threads (8 warps).
// One warp per bin (256 ch: lane -> 8 ch via one LDG.128 per tap).
// Tap tables merge duplicate pixel offsets; zero-weight taps skipped with
// warp-uniform branches. x-taps in fp16 (HFMA2), y-combine in f32x2 (FFMA2).
// Results staged in smem as HALF (one extra rounding), pitch 129 words/bin:
// word k*32+lane holds channel pair (lane*8+2k, lane*8+2k+1). Flush is
// fully coalesced STG.32 in (c,bin) order; 129%32==1 keeps LDS conflict-free.
// ---------------------------------------------------------------------------
extern __shared__ unsigned s_bufu[];

typedef unsigned long long u64t;
union F2U { float2 f; u64t u; };

__global__ __launch_bounds__(256, 6) void roi_align_kernel(const float* __restrict__ boxes,
                                                           float* __restrict__ out)
{
    __shared__ int      s_yoff[ROUT][4];
    __shared__ u64t     s_yw2[ROUT][4];     // packed (wy,wy) f32x2; 0 => skip row
    __shared__ int      s_xoff[ROUT][4];
    __shared__ unsigned s_xwu[ROUT][4];     // (wx,wx) half2 bits;  0 => skip tap

    const int blk = blockIdx.x;
    const int lvl = blk >> 10;
    const int roi = blk & 1023;
    const int tid = threadIdx.x;

    const int   H = c_H[lvl];
    const int   W = c_W[lvl];
    const float S = c_S[lvl];

    // tap tables: threads 0..6 -> y, 32..38 -> x
    if (tid < ROUT || (tid >= 32 && tid < 32 + ROUT)) {
        const bool isY = (tid < ROUT);
        const int  p   = isY ? tid : (tid - 32);
        const float b1 = boxes[roi * 4 + (isY ? 1 : 0)] * S;
        const float b2 = boxes[roi * 4 + (isY ? 3 : 2)] * S;
        const float len  = fmaxf(b2 - b1, 1.0f);
        const int   D    = isY ? H : W;
        const float Df   = (float)D;
        const float step = len * (1.0f / (float)ROUT);
        const int   estr = isY ? (W * CCH) : CCH;   // strides in halves

        int   off[4];
        float wv[4];
#pragma unroll
        for (int s = 0; s < 2; s++) {
            float g   = ((float)(p * 2 + s) + 0.5f) * 0.5f;
            float pos = b1 + step * g;
            bool  v   = (pos >= -1.0f) && (pos <= Df);
            float pc  = fminf(fmaxf(pos, 0.0f), Df - 1.0f);
            int   i0  = (int)floorf(pc);
            int   i1  = min(i0 + 1, D - 1);
            float l   = pc - (float)i0;
            float hgt = 1.0f - l;
            float vw  = v ? 0.5f : 0.0f;   // 0.5*0.5 realizes the sr^2 mean
            off[2 * s]     = i0 * estr;  wv[2 * s]     = hgt * vw;
            off[2 * s + 1] = i1 * estr;  wv[2 * s + 1] = l * vw;
        }
        // merge duplicate offsets (also covers border-clamped i0==i1)
#pragma unroll
        for (int k = 1; k < 4; k++) {
#pragma unroll
            for (int m = 0; m < k; m++) {
                if (off[k] == off[m] && wv[k] != 0.0f && wv[m] != 0.0f) {
                    wv[m] += wv[k];
                    wv[k] = 0.0f;
                }
            }
        }
        if (isY) {
#pragma unroll
            for (int k = 0; k < 4; k++) {
                s_yoff[p][k] = off[k];
                unsigned u = __float_as_uint(wv[k]);
                s_yw2[p][k] = ((u64t)u << 32) | u;     // 0.0f packs to 0
            }
        } else {
#pragma unroll
            for (int k = 0; k < 4; k++) {
                s_xoff[p][k] = off[k];
                __half2 h2 = __float2half2_rn(wv[k]);
                s_xwu[p][k] = *(unsigned*)&h2;          // 0.0f packs to 0
            }
        }
    }
    __syncthreads();

    const int b = roi >> 9;
    const __half* fbase = g_nhwc + c_OFF[lvl] + (size_t)b * H * W * CCH;
    float* outR = out + (size_t)lvl * OUT_LVL_STRIDE + (size_t)roi * ROI_STRIDE;

    const int warp = tid >> 5;
    const int lane = tid & 31;
    const int cbase = lane * 8;     // 8 channels per lane

    for (int bin = warp; bin < BINS; bin += 8) {
        const int ph = bin / 7;
        const int pw = bin - ph * 7;

        u64t acc0 = 0, acc1 = 0, acc2 = 0, acc3 = 0;
#pragma unroll
        for (int i = 0; i < 4; i++) {
            const u64t wy2 = s_yw2[ph][i];
            if (wy2 == 0) continue;                    // warp-uniform: skip 4 LDGs
            const __half* rp = fbase + s_yoff[ph][i] + cbase;
            __half2 r0 = __float2half2_rn(0.f), r1 = r0, r2 = r0, r3 = r0;
#pragma unroll
            for (int j = 0; j < 4; j++) {
                const unsigned wb = s_xwu[pw][j];
                if (wb == 0) continue;                 // warp-uniform: skip 1 LDG
                const __half2 w2 = *(const __half2*)&wb;
                const uint4 v = *(const uint4*)(rp + s_xoff[pw][j]);
                const __half2* hp = (const __half2*)&v;
                r0 = __hfma2(w2, hp[0], r0);
                r1 = __hfma2(w2, hp[1], r1);
                r2 = __hfma2(w2, hp[2], r2);
                r3 = __hfma2(w2, hp[3], r3);
            }
            F2U f0, f1, f2, f3;
            f0.f = __half22float2(r0);
            f1.f = __half22float2(r1);
            f2.f = __half22float2(r2);
            f3.f = __half22float2(r3);
            asm("fma.rn.f32x2 %0, %1, %2, %0;" : "+l"(acc0) : "l"(f0.u), "l"(wy2));
            asm("fma.rn.f32x2 %0, %1, %2, %0;" : "+l"(acc1) : "l"(f1.u), "l"(wy2));
            asm("fma.rn.f32x2 %0, %1, %2, %0;" : "+l"(acc2) : "l"(f2.u), "l"(wy2));
            asm("fma.rn.f32x2 %0, %1, %2, %0;" : "+l"(acc3) : "l"(f3.u), "l"(wy2));
        }

        // stage as half2: word k*32+lane holds channels (cbase+2k, cbase+2k+1)
        F2U o0, o1, o2, o3;
        o0.u = acc0; o1.u = acc1; o2.u = acc2; o3.u = acc3;
        __half2 p0 = __floats2half2_rn(o0.f.x, o0.f.y);
        __half2 p1 = __floats2half2_rn(o1.f.x, o1.f.y);
        __half2 p2 = __floats2half2_rn(o2.f.x, o2.f.y);
        __half2 p3 = __floats2half2_rn(o3.f.x, o3.f.y);
        const int rb = bin * SBUF_PITCHW;
        s_bufu[rb + 0 * 32 + lane] = *(unsigned*)&p0;
        s_bufu[rb + 1 * 32 + lane] = *(unsigned*)&p1;
        s_bufu[rb + 2 * 32 + lane] = *(unsigned*)&p2;
        s_bufu[rb + 3 * 32 + lane] = *(unsigned*)&p3;
    }
    __syncthreads();

    // flush: out element e = c*49 + bin, fully coalesced STG.32.
    // channel c lives in word ((c&7)>>1)*32 + (c>>3) of row bin, half (c&1).
    int e = tid;
    int c = tid / BINS;
    int bin = tid - c * BINS;
#pragma unroll 7
    for (int it = 0; it < BINS; it++) {
        unsigned wbits = s_bufu[bin * SBUF_PITCHW + (((c & 7) >> 1) << 5) + (c >> 3)];
        __half2 h2 = *(__half2*)&wbits;
        float2 f = __half22float2(h2);
        outR[e] = (c & 1) ? f.y : f.x;
        e += 256;
        bin += 11; c += 5;                 // 256 = 5*49 + 11
        if (bin >= BINS) { bin -= BINS; c += 1; }
    }
}

// ---------------------------------------------------------------------------
extern "C" void kernel_launch(void* const* d_in, const int* in_sizes, int n_in,
                              void* d_out, int out_size)
{
    const float* x0 = (const float*)d_in[0];
    const float* x1 = (const float*)d_in[1];
    const float* x2 = (const float*)d_in[2];
    const float* x3 = (const float*)d_in[3];
    const float* boxes = (const float*)d_in[4];
    float* out = (float*)d_out;

    cudaFuncSetAttribute(roi_align_kernel,
                         cudaFuncAttributeMaxDynamicSharedMemorySize, SBUF_BYTES);

    transpose_half_kernel<<<21600, dim3(32, 8)>>>(x0, x1, x2, x3);
    roi_align_kernel<<<NLVL * RTOT, 256, SBUF_BYTES>>>(boxes, out);
}